// round 10
// baseline (speedup 1.0000x reference)
#include <cuda_runtime.h>
#include <cstdint>

#define HR 158
#define HO 156
#define WO 156
#define CH_STRIDE (158*160)

// smem map (bytes)
#define SM_A   0
#define A_BYTES (80*528)             // 80 rows x 132 floats = 42240
#define SM_B0  A_BYTES
#define BHALF  (104*272)             // 104 rows x 68 floats = 28288
#define SM_DS  (SM_B0 + 2*BHALF)     // 98816
#define SMEM_TOTAL (SM_DS + 21*80*4) // 105536

// At: [b][y 158][p 2][m 80][c 128]   (~52 MB)
__device__ __align__(16) float g_At[(size_t)4*158*2*80*128];
// Bt: [b][y2i 198][p 2][n 104][c 128] (~84 MB)
__device__ __align__(16) float g_Bt[(size_t)4*198*2*104*128];
// raw, parity-split rows: [b*441+ch][y 158][p 2][m 80]  (~178 MB)
__device__ __align__(16) float g_raw[(size_t)4*441*158*160];

static __device__ __forceinline__ float to_tf32(float x){
    float r; asm("cvt.rna.tf32.f32 %0, %1;" : "=f"(r) : "f"(x)); return r;
}

// ---------------- Pass 0: transpose/pad to K-major tf32 tiles ----------------
__global__ __launch_bounds__(256) void transA(const float* __restrict__ in1){
    __shared__ float sm[32*193];
    const int y = blockIdx.x, b = blockIdx.y;
    const int tid = threadIdx.x, w = tid >> 5, lane = tid & 31;
    float* outb = g_At + (size_t)((b*158 + y)*2) * (80*128);
    for (int c0 = 0; c0 < 128; c0 += 32){
        __syncthreads();
        for (int idx = tid; idx < 32*192; idx += 256){
            int cl = idx / 192, xx = idx - cl*192;
            sm[cl*193 + xx] = in1[(((size_t)b*128 + c0 + cl)*192 + (y+17))*192 + xx];
        }
        __syncthreads();
        #pragma unroll
        for (int it = 0; it < 20; ++it){
            int combo = w + (it << 3);          // 0..159
            int pp = combo / 80, m = combo - pp*80;
            int xs = 2*m + pp + 17;
            float v = (m <= 78) ? sm[lane*193 + xs] : 0.f;
            outb[((size_t)pp*80 + m)*128 + c0 + lane] = to_tf32(v);
        }
    }
}

__global__ __launch_bounds__(256) void transB(const float* __restrict__ in2){
    __shared__ float sm[32*193];
    const int y2i = blockIdx.x, b = blockIdx.y;
    const int y2 = y2i - 3;
    const bool rowok = (y2 >= 0 && y2 < 192);
    const int tid = threadIdx.x, w = tid >> 5, lane = tid & 31;
    float* outb = g_Bt + (size_t)((b*198 + y2i)*2) * (104*128);
    for (int c0 = 0; c0 < 128; c0 += 32){
        __syncthreads();
        for (int idx = tid; idx < 32*192; idx += 256){
            int cl = idx / 192, xx = idx - cl*192;
            sm[cl*193 + xx] = rowok ?
                in2[(((size_t)b*128 + c0 + cl)*192 + y2)*192 + xx] : 0.f;
        }
        __syncthreads();
        #pragma unroll
        for (int it = 0; it < 26; ++it){
            int combo = w + (it << 3);          // 0..207
            if (combo < 208){
                int pp = combo / 104, n = combo - pp*104;
                int xs = 2*n + pp - 3;
                float v = (xs >= 0 && xs < 192) ? sm[lane*193 + xs] : 0.f;
                outb[((size_t)pp*104 + n)*128 + c0 + lane] = to_tf32(v);
            }
        }
    }
}

// ---------------- helpers ----------------
__device__ __forceinline__ void cpa16(uint32_t dst, const void* src){
    asm volatile("cp.async.cg.shared.global [%0], [%1], 16;" :: "r"(dst), "l"(src));
}
__device__ __forceinline__ void mma8(float* d, const uint32_t* a, uint32_t b0, uint32_t b1){
    asm volatile(
        "mma.sync.aligned.m16n8k8.row.col.f32.tf32.tf32.f32 "
        "{%0,%1,%2,%3}, {%4,%5,%6,%7}, {%8,%9}, {%0,%1,%2,%3};"
        : "+f"(d[0]), "+f"(d[1]), "+f"(d[2]), "+f"(d[3])
        : "r"(a[0]), "r"(a[1]), "r"(a[2]), "r"(a[3]), "r"(b0), "r"(b1));
}

// ---------------- Pass 1: banded tf32 MMA, 8 warps, k-split B, 2 CTA/SM ------
// grid (y 158, p 2, b 4); block 256 = 8 warps.
// 25 band units u=(mt,tt): mt=u/5 m-rows 16mt..+15; n-tile base 16mt+8tt.
// warp w owns units {w, w+8, w+16} (+ u24 for w==0).
extern __shared__ __align__(16) char smem_dyn[];

__global__ __launch_bounds__(256, 2)
void corr_mma(){
    const int y = blockIdx.x, p = blockIdx.y, b = blockIdx.z;
    const int tid = threadIdx.x, w = tid >> 5, lane = tid & 31;
    const int grp = lane >> 2, tig = lane & 3;
    char* smc = smem_dyn;
    const uint32_t sb = (uint32_t)__cvta_generic_to_shared(smc);
    float* Dsm = (float*)(smc + SM_DS);

    const int nu = (w == 0) ? 4 : 3;
    int umt[4], utt[4];
    #pragma unroll
    for (int k = 0; k < 4; ++k){
        int u = (k < 3) ? (w + 8*k) : 24;
        umt[k] = u / 5;
        utt[k] = u - 5*(u/5);
    }

    const float* Ab = g_At + ((size_t)(b*158 + y)*2 + p) * (80*128);
    const size_t bbase = ((size_t)b*198 + y)*2 + p;   // row idx advances by 4 per pane

    // prologue: A fill + B(pane0,kh0) as group 0
    for (int idx = tid; idx < 2560; idx += 256){
        int m = idx >> 5, j = idx & 31;
        cpa16(sb + SM_A + m*528 + j*16, Ab + m*128 + j*4);
    }
    {
        const float* Bb = g_Bt + bbase * (104*128);
        for (int idx = tid; idx < 1664; idx += 256){
            int n = idx >> 4, j = idx & 15;
            cpa16(sb + SM_B0 + n*272 + j*16, (const char*)(Bb + n*128) + j*16);
        }
    }
    asm volatile("cp.async.commit_group;" ::: "memory");

    float dacc[4][4];

    for (int pane = 0; pane <= 20; ++pane){
        #pragma unroll
        for (int k = 0; k < 4; ++k)
            #pragma unroll
            for (int q = 0; q < 4; ++q) dacc[k][q] = 0.f;

        #pragma unroll
        for (int kh = 0; kh < 2; ++kh){
            const int ph = pane*2 + kh;
            if (ph < 41){
                // issue load for phase ph+1
                const int npane = (ph+1) >> 1, nkh = (ph+1) & 1;
                const float* Bb = g_Bt + (bbase + (size_t)npane*4) * (104*128);
                const uint32_t dstb = sb + SM_B0 + ((ph+1) & 1) * BHALF;
                for (int idx = tid; idx < 1664; idx += 256){
                    int n = idx >> 4, j = idx & 15;
                    cpa16(dstb + n*272 + j*16,
                          (const char*)(Bb + n*128 + nkh*64) + j*16);
                }
                asm volatile("cp.async.commit_group;" ::: "memory");
                asm volatile("cp.async.wait_group 1;" ::: "memory");
            } else {
                asm volatile("cp.async.wait_group 0;" ::: "memory");
            }
            __syncthreads();

            const char* bufb = smc + SM_B0 + (ph & 1) * BHALF;
            #pragma unroll
            for (int ksl = 0; ksl < 8; ++ksl){
                const int ks = kh*8 + ksl;
                #pragma unroll
                for (int k = 0; k < 4; ++k){
                    if (k < nu){
                        const uint32_t* pa = (const uint32_t*)(smc + SM_A +
                            (16*umt[k] + grp)*528 + tig*4);
                        uint32_t a[4];
                        a[0] = pa[ks*8];
                        a[1] = pa[ks*8 + 8*132];
                        a[2] = pa[ks*8 + 4];
                        a[3] = pa[ks*8 + 8*132 + 4];
                        const uint32_t* pb = (const uint32_t*)(bufb +
                            (16*umt[k] + 8*utt[k] + grp)*272 + tig*4);
                        mma8(dacc[k], a, pb[ksl*8], pb[ksl*8 + 4]);
                    }
                }
            }
            __syncthreads();
        }

        // band extraction into Dsm[dxi][m]
        #pragma unroll
        for (int k = 0; k < 4; ++k){
            if (k < nu){
                const int m0 = 16*umt[k] + grp;
                const int dx0 = 8*utt[k] + 2*tig - grp;
                if ((unsigned)dx0 < 21u)     Dsm[dx0*80 + m0]     = dacc[k][0];
                if ((unsigned)(dx0+1) < 21u) Dsm[(dx0+1)*80 + m0] = dacc[k][1];
                const int dx2 = dx0 - 8;
                if ((unsigned)dx2 < 21u)     Dsm[dx2*80 + m0+8]     = dacc[k][2];
                if ((unsigned)(dx2+1) < 21u) Dsm[(dx2+1)*80 + m0+8] = dacc[k][3];
            }
        }
        __syncthreads();

        // coalesced store of 21 x 80 band rows
        if (tid < 240){
            const int mloc = tid % 80;
            const int dbase = tid / 80;   // 0..2
            float* orow = g_raw + ((size_t)(b*441 + pane*21) * 158 + y) * 160
                          + p*80 + mloc;
            #pragma unroll
            for (int kk = 0; kk < 7; ++kk){
                int dxi = dbase + 3*kk;
                orow[(size_t)dxi * CH_STRIDE] = Dsm[dxi*80 + mloc];
            }
        }
        // next pane's first __syncthreads (after wait_group) orders store vs reuse
    }
}

// ---------------- Pass 2: 3x3 box sum / 1152 on parity-split rows ----------------
__global__ void corr_pass2(float* __restrict__ out){
    const int tid = threadIdx.x;            // 156
    const int qx = tid % 39;
    const int qy = blockIdx.y * 4 + tid / 39;
    const int ch = blockIdx.z;
    if (qy >= 39) return;
    const int i0 = qy * 4, j0 = qx * 4, m0 = qx * 2;
    const float inv = 1.0f / 1152.0f;

    const float* rb = g_raw + (size_t)ch * CH_STRIDE;
    float w6[6][4];
    #pragma unroll
    for (int rr = 0; rr < 6; ++rr){
        const float* row = rb + (size_t)(i0 + rr) * 160;
        float2 u = *(const float2*)(row + m0);
        float  u2 = row[m0 + 2];
        float2 v = *(const float2*)(row + 80 + m0);
        float  v2 = row[80 + m0 + 2];
        w6[rr][0] = u.x + v.x + u.y;
        w6[rr][1] = v.x + u.y + v.y;
        w6[rr][2] = u.y + v.y + u2;
        w6[rr][3] = v.y + u2 + v2;
    }
    float* ob = out + (size_t)ch * HO * WO + j0;
    #pragma unroll
    for (int i = 0; i < 4; ++i){
        float4 o;
        o.x = (w6[i][0] + w6[i+1][0] + w6[i+2][0]) * inv;
        o.y = (w6[i][1] + w6[i+1][1] + w6[i+2][1]) * inv;
        o.z = (w6[i][2] + w6[i+1][2] + w6[i+2][2]) * inv;
        o.w = (w6[i][3] + w6[i+1][3] + w6[i+2][3]) * inv;
        *reinterpret_cast<float4*>(ob + (size_t)(i0 + i) * WO) = o;
    }
}

extern "C" void kernel_launch(void* const* d_in, const int* in_sizes, int n_in,
                              void* d_out, int out_size){
    const float* in1 = (const float*)d_in[0];
    const float* in2 = (const float*)d_in[1];
    float* out = (float*)d_out;

    transA<<<dim3(158, 4), 256>>>(in1);
    transB<<<dim3(198, 4), 256>>>(in2);

    cudaFuncSetAttribute(corr_mma,
                         cudaFuncAttributeMaxDynamicSharedMemorySize, SMEM_TOTAL);
    corr_mma<<<dim3(158, 2, 4), 256, SMEM_TOTAL>>>();

    dim3 g2(1, 10, 4*441), b2(156);
    corr_pass2<<<g2, b2>>>(out);
}

// round 11
// speedup vs baseline: 1.4044x; 1.4044x over previous
#include <cuda_runtime.h>
#include <cstdint>

#define HR 158
#define HO 156
#define WO 156
#define CH_STRIDE (158*160)

// smem map (bytes)
#define SM_A   0
#define A_BYTES (80*528)             // 80 rows x 132 floats
#define SM_B0  A_BYTES               // 42240
#define BHALF  (104*272)             // 104 rows x 68 floats = 28288
#define SM_DS  (SM_B0 + 2*BHALF)     // 98816
#define SMEM_TOTAL (SM_DS + 21*80*4) // 105536  (x2 CTAs = 206 KB < 228 KB)

// At: [b][y 158][p 2][m 80][c 128]   (~52 MB)
__device__ __align__(16) float g_At[(size_t)4*158*2*80*128];
// Bt: [b][y2i 198][p 2][n 104][c 128] (~84 MB)
__device__ __align__(16) float g_Bt[(size_t)4*198*2*104*128];
// raw, parity-split rows: [b*441+ch][y 158][p 2][m 80]  (~178 MB)
__device__ __align__(16) float g_raw[(size_t)4*441*158*160];

static __device__ __forceinline__ float to_tf32(float x){
    float r; asm("cvt.rna.tf32.f32 %0, %1;" : "=f"(r) : "f"(x)); return r;
}

// ---------------- Pass 0: transpose/pad to K-major tf32 tiles ----------------
__global__ __launch_bounds__(256) void transA(const float* __restrict__ in1){
    __shared__ float sm[32*193];
    const int y = blockIdx.x, b = blockIdx.y;
    const int tid = threadIdx.x, w = tid >> 5, lane = tid & 31;
    float* outb = g_At + (size_t)((b*158 + y)*2) * (80*128);
    for (int c0 = 0; c0 < 128; c0 += 32){
        __syncthreads();
        for (int idx = tid; idx < 32*192; idx += 256){
            int cl = idx / 192, xx = idx - cl*192;
            sm[cl*193 + xx] = in1[(((size_t)b*128 + c0 + cl)*192 + (y+17))*192 + xx];
        }
        __syncthreads();
        #pragma unroll
        for (int it = 0; it < 20; ++it){
            int combo = w + (it << 3);          // 0..159
            int pp = combo / 80, m = combo - pp*80;
            int xs = 2*m + pp + 17;
            float v = (m <= 78) ? sm[lane*193 + xs] : 0.f;
            outb[((size_t)pp*80 + m)*128 + c0 + lane] = to_tf32(v);
        }
    }
}

__global__ __launch_bounds__(256) void transB(const float* __restrict__ in2){
    __shared__ float sm[32*193];
    const int y2i = blockIdx.x, b = blockIdx.y;
    const int y2 = y2i - 3;
    const bool rowok = (y2 >= 0 && y2 < 192);
    const int tid = threadIdx.x, w = tid >> 5, lane = tid & 31;
    float* outb = g_Bt + (size_t)((b*198 + y2i)*2) * (104*128);
    for (int c0 = 0; c0 < 128; c0 += 32){
        __syncthreads();
        for (int idx = tid; idx < 32*192; idx += 256){
            int cl = idx / 192, xx = idx - cl*192;
            sm[cl*193 + xx] = rowok ?
                in2[(((size_t)b*128 + c0 + cl)*192 + y2)*192 + xx] : 0.f;
        }
        __syncthreads();
        #pragma unroll
        for (int it = 0; it < 26; ++it){
            int combo = w + (it << 3);          // 0..207
            if (combo < 208){
                int pp = combo / 104, n = combo - pp*104;
                int xs = 2*n + pp - 3;
                float v = (xs >= 0 && xs < 192) ? sm[lane*193 + xs] : 0.f;
                outb[((size_t)pp*104 + n)*128 + c0 + lane] = to_tf32(v);
            }
        }
    }
}

// ---------------- helpers ----------------
__device__ __forceinline__ void cpa16(uint32_t dst, const void* src){
    asm volatile("cp.async.cg.shared.global [%0], [%1], 16;" :: "r"(dst), "l"(src));
}
__device__ __forceinline__ void mma8(float* d, const uint32_t* a, uint32_t b0, uint32_t b1){
    asm volatile(
        "mma.sync.aligned.m16n8k8.row.col.f32.tf32.tf32.f32 "
        "{%0,%1,%2,%3}, {%4,%5,%6,%7}, {%8,%9}, {%0,%1,%2,%3};"
        : "+f"(d[0]), "+f"(d[1]), "+f"(d[2]), "+f"(d[3])
        : "r"(a[0]), "r"(a[1]), "r"(a[2]), "r"(a[3]), "r"(b0), "r"(b1));
}

// ---------------- Pass 1: banded tf32 MMA, warp=m-tile, k-split, 2 CTA/SM ----
// grid (y 158, p 2, b 4); block 160 = 5 warps, warp w owns m-rows 16w..16w+15
// and its 5 diagonal n8-tiles. B pane loaded in two 64-channel halves.
extern __shared__ __align__(16) char smem_dyn[];

__global__ __launch_bounds__(160, 2)
void corr_mma(){
    const int y = blockIdx.x, p = blockIdx.y, b = blockIdx.z;
    const int tid = threadIdx.x, w = tid >> 5, lane = tid & 31;
    const int grp = lane >> 2, tig = lane & 3;
    char* smc = smem_dyn;
    const uint32_t sb = (uint32_t)__cvta_generic_to_shared(smc);
    float* Dsm = (float*)(smc + SM_DS);

    const float* Ab = g_At + ((size_t)(b*158 + y)*2 + p) * (80*128);
    const size_t bbase = ((size_t)b*198 + y)*2 + p;

    // prologue: A fill + B(pane0, kh0) as group 0
    for (int idx = tid; idx < 2560; idx += 160){
        int m = idx >> 5, j = idx & 31;
        cpa16(sb + SM_A + m*528 + j*16, Ab + m*128 + j*4);
    }
    {
        const float* Bb = g_Bt + bbase * (104*128);
        for (int idx = tid; idx < 1664; idx += 160){
            int n = idx >> 4, j = idx & 15;
            cpa16(sb + SM_B0 + n*272 + j*16, (const char*)(Bb + n*128) + j*16);
        }
    }
    asm volatile("cp.async.commit_group;" ::: "memory");

    const uint32_t* pa = (const uint32_t*)(smc + SM_A + (16*w + grp)*528 + tig*4);
    const int m0 = 16*w + grp;

    for (int pane = 0; pane <= 20; ++pane){
        float dacc[5][4];
        #pragma unroll
        for (int t = 0; t < 5; ++t)
            #pragma unroll
            for (int q = 0; q < 4; ++q) dacc[t][q] = 0.f;

        #pragma unroll
        for (int kh = 0; kh < 2; ++kh){
            const int ph = pane*2 + kh;
            if (ph < 41){
                const int npane = (ph+1) >> 1, nkh = (ph+1) & 1;
                const float* Bb = g_Bt + (bbase + (size_t)npane*4) * (104*128);
                const uint32_t dstb = sb + SM_B0 + ((ph+1) & 1) * BHALF;
                for (int idx = tid; idx < 1664; idx += 160){
                    int n = idx >> 4, j = idx & 15;
                    cpa16(dstb + n*272 + j*16,
                          (const char*)(Bb + n*128 + nkh*64) + j*16);
                }
                asm volatile("cp.async.commit_group;" ::: "memory");
                asm volatile("cp.async.wait_group 1;" ::: "memory");
            } else {
                asm volatile("cp.async.wait_group 0;" ::: "memory");
            }
            __syncthreads();

            const uint32_t* pb0 = (const uint32_t*)(smc + SM_B0 + (ph & 1)*BHALF +
                                                    (16*w + grp)*272 + tig*4);
            #pragma unroll
            for (int ksl = 0; ksl < 8; ++ksl){
                const int ks = kh*8 + ksl;
                uint32_t a[4];
                a[0] = pa[ks*8];
                a[1] = pa[ks*8 + 8*132];
                a[2] = pa[ks*8 + 4];
                a[3] = pa[ks*8 + 8*132 + 4];
                #pragma unroll
                for (int t = 0; t < 5; ++t){
                    const uint32_t* pb = pb0 + t*8*68;
                    mma8(dacc[t], a, pb[ksl*8], pb[ksl*8 + 4]);
                }
            }
            __syncthreads();
        }

        // band extraction into Dsm[dxi][m]
        #pragma unroll
        for (int t = 0; t < 5; ++t){
            const int dx0 = 8*t + 2*tig - grp;
            if ((unsigned)dx0 < 21u)     Dsm[dx0*80 + m0]     = dacc[t][0];
            if ((unsigned)(dx0+1) < 21u) Dsm[(dx0+1)*80 + m0] = dacc[t][1];
            const int dx2 = dx0 - 8;
            if ((unsigned)dx2 < 21u)     Dsm[dx2*80 + m0+8]     = dacc[t][2];
            if ((unsigned)(dx2+1) < 21u) Dsm[(dx2+1)*80 + m0+8] = dacc[t][3];
        }
        __syncthreads();

        // coalesced store of 21 x 80 band rows (160 threads)
        {
            const int mloc = (tid >= 80) ? tid - 80 : tid;
            const int dxi0 = (tid >= 80) ? 1 : 0;
            float* orow = g_raw + ((size_t)(b*441 + pane*21) * 158 + y) * 160
                          + p*80 + mloc;
            #pragma unroll
            for (int k = 0; k < 10; ++k){
                int dxi = 2*k + dxi0;
                orow[(size_t)dxi * CH_STRIDE] = Dsm[dxi*80 + mloc];
            }
            if (dxi0 == 0)
                orow[(size_t)20 * CH_STRIDE] = Dsm[20*80 + mloc];
        }
        // next pane's first __syncthreads orders these reads before Dsm rewrite
    }
}

// ---------------- Pass 2: 3x3 box sum / 1152 on parity-split rows ----------------
__global__ void corr_pass2(float* __restrict__ out){
    const int tid = threadIdx.x;            // 156
    const int qx = tid % 39;
    const int qy = blockIdx.y * 4 + tid / 39;
    const int ch = blockIdx.z;
    if (qy >= 39) return;
    const int i0 = qy * 4, j0 = qx * 4, m0 = qx * 2;
    const float inv = 1.0f / 1152.0f;

    const float* rb = g_raw + (size_t)ch * CH_STRIDE;
    float w6[6][4];
    #pragma unroll
    for (int rr = 0; rr < 6; ++rr){
        const float* row = rb + (size_t)(i0 + rr) * 160;
        float2 u = *(const float2*)(row + m0);
        float  u2 = row[m0 + 2];
        float2 v = *(const float2*)(row + 80 + m0);
        float  v2 = row[80 + m0 + 2];
        w6[rr][0] = u.x + v.x + u.y;
        w6[rr][1] = v.x + u.y + v.y;
        w6[rr][2] = u.y + v.y + u2;
        w6[rr][3] = v.y + u2 + v2;
    }
    float* ob = out + (size_t)ch * HO * WO + j0;
    #pragma unroll
    for (int i = 0; i < 4; ++i){
        float4 o;
        o.x = (w6[i][0] + w6[i+1][0] + w6[i+2][0]) * inv;
        o.y = (w6[i][1] + w6[i+1][1] + w6[i+2][1]) * inv;
        o.z = (w6[i][2] + w6[i+1][2] + w6[i+2][2]) * inv;
        o.w = (w6[i][3] + w6[i+1][3] + w6[i+2][3]) * inv;
        *reinterpret_cast<float4*>(ob + (size_t)(i0 + i) * WO) = o;
    }
}

extern "C" void kernel_launch(void* const* d_in, const int* in_sizes, int n_in,
                              void* d_out, int out_size){
    const float* in1 = (const float*)d_in[0];
    const float* in2 = (const float*)d_in[1];
    float* out = (float*)d_out;

    transA<<<dim3(158, 4), 256>>>(in1);
    transB<<<dim3(198, 4), 256>>>(in2);

    cudaFuncSetAttribute(corr_mma,
                         cudaFuncAttributeMaxDynamicSharedMemorySize, SMEM_TOTAL);
    corr_mma<<<dim3(158, 2, 4), 160, SMEM_TOTAL>>>();

    dim3 g2(1, 10, 4*441), b2(156);
    corr_pass2<<<g2, b2>>>(out);
}

// round 12
// speedup vs baseline: 1.5428x; 1.0986x over previous
#include <cuda_runtime.h>
#include <cstdint>

#define HR 158
#define HO 156
#define WO 156
#define CH_STRIDE (158*160)

// smem map (bytes)
#define SM_A   0
#define A_BYTES (80*528)             // 80 rows x 132 floats
#define SM_B0  A_BYTES               // 42240
#define BHALF  (104*272)             // 104 rows x 68 floats = 28288
#define SM_DS  (SM_B0 + 2*BHALF)     // 98816
#define SMEM_TOTAL (SM_DS + 21*80*4) // 105536  (x2 CTAs = 206 KB < 228 KB)

// At: [b][y 158][p 2][m 80][c 128]   (~52 MB)
__device__ __align__(16) float g_At[(size_t)4*158*2*80*128];
// Bt: [b][y2i 198][p 2][n 104][c 128] (~84 MB)
__device__ __align__(16) float g_Bt[(size_t)4*198*2*104*128];
// raw, parity-split rows: [b*441+ch][y 158][p 2][m 80]  (~178 MB)
__device__ __align__(16) float g_raw[(size_t)4*441*158*160];

static __device__ __forceinline__ float to_tf32(float x){
    float r; asm("cvt.rna.tf32.f32 %0, %1;" : "=f"(r) : "f"(x)); return r;
}

// ---------------- Pass 0: fused transpose/pad to K-major tf32 tiles ----------
// grid.x: [0,158) -> A row y ; [158,356) -> B row y2i. grid.y = b.
__global__ __launch_bounds__(256) void transAB(const float* __restrict__ in1,
                                               const float* __restrict__ in2){
    __shared__ float sm[32*193];
    const int bx = blockIdx.x, b = blockIdx.y;
    const int tid = threadIdx.x, w = tid >> 5, lane = tid & 31;

    if (bx < 158){
        const int y = bx;
        float* outb = g_At + (size_t)((b*158 + y)*2) * (80*128);
        for (int c0 = 0; c0 < 128; c0 += 32){
            __syncthreads();
            for (int idx = tid; idx < 32*192; idx += 256){
                int cl = idx / 192, xx = idx - cl*192;
                sm[cl*193 + xx] = in1[(((size_t)b*128 + c0 + cl)*192 + (y+17))*192 + xx];
            }
            __syncthreads();
            #pragma unroll
            for (int it = 0; it < 20; ++it){
                int combo = w + (it << 3);          // 0..159
                int pp = combo / 80, m = combo - pp*80;
                int xs = 2*m + pp + 17;
                float v = (m <= 78) ? sm[lane*193 + xs] : 0.f;
                outb[((size_t)pp*80 + m)*128 + c0 + lane] = to_tf32(v);
            }
        }
    } else {
        const int y2i = bx - 158;
        const int y2 = y2i - 3;
        const bool rowok = (y2 >= 0 && y2 < 192);
        float* outb = g_Bt + (size_t)((b*198 + y2i)*2) * (104*128);
        for (int c0 = 0; c0 < 128; c0 += 32){
            __syncthreads();
            for (int idx = tid; idx < 32*192; idx += 256){
                int cl = idx / 192, xx = idx - cl*192;
                sm[cl*193 + xx] = rowok ?
                    in2[(((size_t)b*128 + c0 + cl)*192 + y2)*192 + xx] : 0.f;
            }
            __syncthreads();
            #pragma unroll
            for (int it = 0; it < 26; ++it){
                int combo = w + (it << 3);          // 0..207
                if (combo < 208){
                    int pp = combo / 104, n = combo - pp*104;
                    int xs = 2*n + pp - 3;
                    float v = (xs >= 0 && xs < 192) ? sm[lane*193 + xs] : 0.f;
                    outb[((size_t)pp*104 + n)*128 + c0 + lane] = to_tf32(v);
                }
            }
        }
    }
}

// ---------------- helpers ----------------
__device__ __forceinline__ void cpa16(uint32_t dst, const void* src){
    asm volatile("cp.async.cg.shared.global [%0], [%1], 16;" :: "r"(dst), "l"(src));
}
__device__ __forceinline__ void mma8(float* d, const uint32_t* a, uint32_t b0, uint32_t b1){
    asm volatile(
        "mma.sync.aligned.m16n8k8.row.col.f32.tf32.tf32.f32 "
        "{%0,%1,%2,%3}, {%4,%5,%6,%7}, {%8,%9}, {%0,%1,%2,%3};"
        : "+f"(d[0]), "+f"(d[1]), "+f"(d[2]), "+f"(d[3])
        : "r"(a[0]), "r"(a[1]), "r"(a[2]), "r"(a[3]), "r"(b0), "r"(b1));
}

// ---------------- Pass 1: banded tf32 MMA, A-in-regs, 3 syncs/pane ----------
// grid (y 158, p 2, b 4); block 160 = 5 warps, warp w owns m-rows 16w..16w+15
// and its 5 diagonal n8-tiles. B pane loaded in two 64-channel halves.
extern __shared__ __align__(16) char smem_dyn[];

__global__ __launch_bounds__(160, 2)
void corr_mma(){
    const int y = blockIdx.x, p = blockIdx.y, b = blockIdx.z;
    const int tid = threadIdx.x, w = tid >> 5, lane = tid & 31;
    const int grp = lane >> 2, tig = lane & 3;
    char* smc = smem_dyn;
    const uint32_t sb = (uint32_t)__cvta_generic_to_shared(smc);
    float* Dsm = (float*)(smc + SM_DS);

    const float* Ab = g_At + ((size_t)(b*158 + y)*2 + p) * (80*128);
    const size_t bbase = ((size_t)b*198 + y)*2 + p;

    // prologue: A fill + B(pane0, kh0) as group 0
    for (int idx = tid; idx < 2560; idx += 160){
        int m = idx >> 5, j = idx & 31;
        cpa16(sb + SM_A + m*528 + j*16, Ab + m*128 + j*4);
    }
    {
        const float* Bb = g_Bt + bbase * (104*128);
        for (int idx = tid; idx < 1664; idx += 160){
            int n = idx >> 4, j = idx & 15;
            cpa16(sb + SM_B0 + n*272 + j*16, (const char*)(Bb + n*128) + j*16);
        }
    }
    asm volatile("cp.async.commit_group;" ::: "memory");

    const uint32_t* pa = (const uint32_t*)(smc + SM_A + (16*w + grp)*528 + tig*4);
    const int m0 = 16*w + grp;

    uint32_t areg[64];   // A fragments for all 16 k-steps, loaded once

    for (int pane = 0; pane <= 20; ++pane){
        float dacc[5][4];
        #pragma unroll
        for (int t = 0; t < 5; ++t)
            #pragma unroll
            for (int q = 0; q < 4; ++q) dacc[t][q] = 0.f;

        #pragma unroll
        for (int kh = 0; kh < 2; ++kh){
            const int ph = pane*2 + kh;

            // buffer ph is the only group in flight
            asm volatile("cp.async.wait_group 0;" ::: "memory");
            __syncthreads();

            if (pane == 0 && kh == 0){
                #pragma unroll
                for (int ks = 0; ks < 16; ++ks){
                    areg[ks*4+0] = pa[ks*8];
                    areg[ks*4+1] = pa[ks*8 + 8*132];
                    areg[ks*4+2] = pa[ks*8 + 4];
                    areg[ks*4+3] = pa[ks*8 + 8*132 + 4];
                }
            }

            if (ph < 41){
                const int npane = (ph+1) >> 1, nkh = (ph+1) & 1;
                const float* Bb = g_Bt + (bbase + (size_t)npane*4) * (104*128);
                const uint32_t dstb = sb + SM_B0 + ((ph+1) & 1) * BHALF;
                for (int idx = tid; idx < 1664; idx += 160){
                    int n = idx >> 4, j = idx & 15;
                    cpa16(dstb + n*272 + j*16,
                          (const char*)(Bb + n*128 + nkh*64) + j*16);
                }
                asm volatile("cp.async.commit_group;" ::: "memory");
            }

            const uint32_t* pb0 = (const uint32_t*)(smc + SM_B0 + (ph & 1)*BHALF +
                                                    (16*w + grp)*272 + tig*4);
            #pragma unroll
            for (int ksl = 0; ksl < 8; ++ksl){
                const uint32_t* a = &areg[(kh*8 + ksl)*4];
                #pragma unroll
                for (int t = 0; t < 5; ++t){
                    const uint32_t* pb = pb0 + t*8*68;
                    mma8(dacc[t], a, pb[ksl*8], pb[ksl*8 + 4]);
                }
            }
            // no bottom sync: next phase's top sync orders buffer reuse
        }

        // band extraction into Dsm[dxi][m]
        #pragma unroll
        for (int t = 0; t < 5; ++t){
            const int dx0 = 8*t + 2*tig - grp;
            if ((unsigned)dx0 < 21u)     Dsm[dx0*80 + m0]     = dacc[t][0];
            if ((unsigned)(dx0+1) < 21u) Dsm[(dx0+1)*80 + m0] = dacc[t][1];
            const int dx2 = dx0 - 8;
            if ((unsigned)dx2 < 21u)     Dsm[dx2*80 + m0+8]     = dacc[t][2];
            if ((unsigned)(dx2+1) < 21u) Dsm[(dx2+1)*80 + m0+8] = dacc[t][3];
        }
        __syncthreads();

        // coalesced store of 21 x 80 band rows (160 threads)
        {
            const int mloc = (tid >= 80) ? tid - 80 : tid;
            const int dxi0 = (tid >= 80) ? 1 : 0;
            float* orow = g_raw + ((size_t)(b*441 + pane*21) * 158 + y) * 160
                          + p*80 + mloc;
            #pragma unroll
            for (int k = 0; k < 10; ++k){
                int dxi = 2*k + dxi0;
                orow[(size_t)dxi * CH_STRIDE] = Dsm[dxi*80 + mloc];
            }
            if (dxi0 == 0)
                orow[(size_t)20 * CH_STRIDE] = Dsm[20*80 + mloc];
        }
        // next pane's top sync orders these Dsm reads before rewrite
    }
}

// ---------------- Pass 2: 3x3 box sum / 1152 on parity-split rows ----------------
__global__ void corr_pass2(float* __restrict__ out){
    const int tid = threadIdx.x;            // 156
    const int qx = tid % 39;
    const int qy = blockIdx.y * 4 + tid / 39;
    const int ch = blockIdx.z;
    if (qy >= 39) return;
    const int i0 = qy * 4, j0 = qx * 4, m0 = qx * 2;
    const float inv = 1.0f / 1152.0f;

    const float* rb = g_raw + (size_t)ch * CH_STRIDE;
    float w6[6][4];
    #pragma unroll
    for (int rr = 0; rr < 6; ++rr){
        const float* row = rb + (size_t)(i0 + rr) * 160;
        float2 u = *(const float2*)(row + m0);
        float  u2 = row[m0 + 2];
        float2 v = *(const float2*)(row + 80 + m0);
        float  v2 = row[80 + m0 + 2];
        w6[rr][0] = u.x + v.x + u.y;
        w6[rr][1] = v.x + u.y + v.y;
        w6[rr][2] = u.y + v.y + u2;
        w6[rr][3] = v.y + u2 + v2;
    }
    float* ob = out + (size_t)ch * HO * WO + j0;
    #pragma unroll
    for (int i = 0; i < 4; ++i){
        float4 o;
        o.x = (w6[i][0] + w6[i+1][0] + w6[i+2][0]) * inv;
        o.y = (w6[i][1] + w6[i+1][1] + w6[i+2][1]) * inv;
        o.z = (w6[i][2] + w6[i+1][2] + w6[i+2][2]) * inv;
        o.w = (w6[i][3] + w6[i+1][3] + w6[i+2][3]) * inv;
        *reinterpret_cast<float4*>(ob + (size_t)(i0 + i) * WO) = o;
    }
}

extern "C" void kernel_launch(void* const* d_in, const int* in_sizes, int n_in,
                              void* d_out, int out_size){
    const float* in1 = (const float*)d_in[0];
    const float* in2 = (const float*)d_in[1];
    float* out = (float*)d_out;

    transAB<<<dim3(356, 4), 256>>>(in1, in2);

    cudaFuncSetAttribute(corr_mma,
                         cudaFuncAttributeMaxDynamicSharedMemorySize, SMEM_TOTAL);
    corr_mma<<<dim3(158, 2, 4), 160, SMEM_TOTAL>>>();

    dim3 g2(1, 10, 4*441), b2(156);
    corr_pass2<<<g2, b2>>>(out);
}

// round 13
// speedup vs baseline: 1.6468x; 1.0674x over previous
#include <cuda_runtime.h>
#include <cstdint>

#define HR 158
#define HO 156
#define WO 156
#define CH_STRIDE (158*160)

// smem map (bytes): B double-buffer + band tile only (A lives in registers)
#define SM_B0  0
#define BHALF  (104*272)             // 104 rows x 68 floats = 28288
#define SM_DS  (2*BHALF)             // 56576
#define SMEM_TOTAL (SM_DS + 21*80*4) // 63296  (x3 CTAs = 189.9 KB < 228 KB)

// At: [b][y 158][p 2][m 80][c 128]   (~52 MB)
__device__ __align__(16) float g_At[(size_t)4*158*2*80*128];
// Bt: [b][y2i 198][p 2][n 104][c 128] (~84 MB)
__device__ __align__(16) float g_Bt[(size_t)4*198*2*104*128];
// raw, parity-split rows: [b*441+ch][y 158][p 2][m 80]  (~178 MB)
__device__ __align__(16) float g_raw[(size_t)4*441*158*160];

static __device__ __forceinline__ float to_tf32(float x){
    float r; asm("cvt.rna.tf32.f32 %0, %1;" : "=f"(r) : "f"(x)); return r;
}

// ---------------- Pass 0: fused transpose/pad to K-major tf32 tiles ----------
__global__ __launch_bounds__(256) void transAB(const float* __restrict__ in1,
                                               const float* __restrict__ in2){
    __shared__ float sm[32*193];
    const int bx = blockIdx.x, b = blockIdx.y;
    const int tid = threadIdx.x, w = tid >> 5, lane = tid & 31;

    if (bx < 158){
        const int y = bx;
        float* outb = g_At + (size_t)((b*158 + y)*2) * (80*128);
        for (int c0 = 0; c0 < 128; c0 += 32){
            __syncthreads();
            for (int idx = tid; idx < 32*192; idx += 256){
                int cl = idx / 192, xx = idx - cl*192;
                sm[cl*193 + xx] = in1[(((size_t)b*128 + c0 + cl)*192 + (y+17))*192 + xx];
            }
            __syncthreads();
            #pragma unroll
            for (int it = 0; it < 20; ++it){
                int combo = w + (it << 3);          // 0..159
                int pp = combo / 80, m = combo - pp*80;
                int xs = 2*m + pp + 17;
                float v = (m <= 78) ? sm[lane*193 + xs] : 0.f;
                outb[((size_t)pp*80 + m)*128 + c0 + lane] = to_tf32(v);
            }
        }
    } else {
        const int y2i = bx - 158;
        const int y2 = y2i - 3;
        const bool rowok = (y2 >= 0 && y2 < 192);
        float* outb = g_Bt + (size_t)((b*198 + y2i)*2) * (104*128);
        for (int c0 = 0; c0 < 128; c0 += 32){
            __syncthreads();
            for (int idx = tid; idx < 32*192; idx += 256){
                int cl = idx / 192, xx = idx - cl*192;
                sm[cl*193 + xx] = rowok ?
                    in2[(((size_t)b*128 + c0 + cl)*192 + y2)*192 + xx] : 0.f;
            }
            __syncthreads();
            #pragma unroll
            for (int it = 0; it < 26; ++it){
                int combo = w + (it << 3);          // 0..207
                if (combo < 208){
                    int pp = combo / 104, n = combo - pp*104;
                    int xs = 2*n + pp - 3;
                    float v = (xs >= 0 && xs < 192) ? sm[lane*193 + xs] : 0.f;
                    outb[((size_t)pp*104 + n)*128 + c0 + lane] = to_tf32(v);
                }
            }
        }
    }
}

// ---------------- helpers ----------------
__device__ __forceinline__ void cpa16(uint32_t dst, const void* src){
    asm volatile("cp.async.cg.shared.global [%0], [%1], 16;" :: "r"(dst), "l"(src));
}
__device__ __forceinline__ void mma8(float* d, const uint32_t* a, uint32_t b0, uint32_t b1){
    asm volatile(
        "mma.sync.aligned.m16n8k8.row.col.f32.tf32.tf32.f32 "
        "{%0,%1,%2,%3}, {%4,%5,%6,%7}, {%8,%9}, {%0,%1,%2,%3};"
        : "+f"(d[0]), "+f"(d[1]), "+f"(d[2]), "+f"(d[3])
        : "r"(a[0]), "r"(a[1]), "r"(a[2]), "r"(a[3]), "r"(b0), "r"(b1));
}

// ---------------- Pass 1: banded tf32 MMA, A-in-regs from gmem, 3 CTA/SM ----
// grid (y 158, p 2, b 4); block 160 = 5 warps, warp w owns m-rows 16w..16w+15
// and its 5 diagonal n8-tiles. B pane loaded in two 64-channel halves.
extern __shared__ __align__(16) char smem_dyn[];

__global__ __launch_bounds__(160, 3)
void corr_mma(){
    const int y = blockIdx.x, p = blockIdx.y, b = blockIdx.z;
    const int tid = threadIdx.x, w = tid >> 5, lane = tid & 31;
    const int grp = lane >> 2, tig = lane & 3;
    char* smc = smem_dyn;
    const uint32_t sb = (uint32_t)__cvta_generic_to_shared(smc);
    float* Dsm = (float*)(smc + SM_DS);

    const float* Ab = g_At + ((size_t)(b*158 + y)*2 + p) * (80*128);
    const size_t bbase = ((size_t)b*198 + y)*2 + p;
    const int m0 = 16*w + grp;

    // prologue: B(pane0, kh0) cp.async as group 0
    {
        const float* Bb = g_Bt + bbase * (104*128);
        for (int idx = tid; idx < 1664; idx += 160){
            int n = idx >> 4, j = idx & 15;
            cpa16(sb + SM_B0 + n*272 + j*16, (const char*)(Bb + n*128) + j*16);
        }
    }
    asm volatile("cp.async.commit_group;" ::: "memory");

    // A fragments straight from gmem (tf32 already applied), once per block
    uint32_t areg[64];
    {
        const uint32_t* Ar0 = (const uint32_t*)(Ab + m0*128 + tig);
        const uint32_t* Ar1 = (const uint32_t*)(Ab + (m0+8)*128 + tig);
        #pragma unroll
        for (int ks = 0; ks < 16; ++ks){
            areg[ks*4+0] = __ldg(&Ar0[ks*8]);
            areg[ks*4+1] = __ldg(&Ar1[ks*8]);
            areg[ks*4+2] = __ldg(&Ar0[ks*8 + 4]);
            areg[ks*4+3] = __ldg(&Ar1[ks*8 + 4]);
        }
    }

    for (int pane = 0; pane <= 20; ++pane){
        float dacc[5][4];
        #pragma unroll
        for (int t = 0; t < 5; ++t)
            #pragma unroll
            for (int q = 0; q < 4; ++q) dacc[t][q] = 0.f;

        #pragma unroll
        for (int kh = 0; kh < 2; ++kh){
            const int ph = pane*2 + kh;

            // buffer ph is the only group in flight
            asm volatile("cp.async.wait_group 0;" ::: "memory");
            __syncthreads();

            if (ph < 41){
                const int npane = (ph+1) >> 1, nkh = (ph+1) & 1;
                const float* Bb = g_Bt + (bbase + (size_t)npane*4) * (104*128);
                const uint32_t dstb = sb + SM_B0 + ((ph+1) & 1) * BHALF;
                for (int idx = tid; idx < 1664; idx += 160){
                    int n = idx >> 4, j = idx & 15;
                    cpa16(dstb + n*272 + j*16,
                          (const char*)(Bb + n*128 + nkh*64) + j*16);
                }
                asm volatile("cp.async.commit_group;" ::: "memory");
            }

            const uint32_t* pb0 = (const uint32_t*)(smc + SM_B0 + (ph & 1)*BHALF +
                                                    (16*w + grp)*272 + tig*4);
            #pragma unroll
            for (int ksl = 0; ksl < 8; ++ksl){
                const uint32_t* a = &areg[(kh*8 + ksl)*4];
                #pragma unroll
                for (int t = 0; t < 5; ++t){
                    const uint32_t* pb = pb0 + t*8*68;
                    mma8(dacc[t], a, pb[ksl*8], pb[ksl*8 + 4]);
                }
            }
            // no bottom sync: next phase's top sync orders buffer reuse
        }

        // band extraction into Dsm[dxi][m]
        #pragma unroll
        for (int t = 0; t < 5; ++t){
            const int dx0 = 8*t + 2*tig - grp;
            if ((unsigned)dx0 < 21u)     Dsm[dx0*80 + m0]     = dacc[t][0];
            if ((unsigned)(dx0+1) < 21u) Dsm[(dx0+1)*80 + m0] = dacc[t][1];
            const int dx2 = dx0 - 8;
            if ((unsigned)dx2 < 21u)     Dsm[dx2*80 + m0+8]     = dacc[t][2];
            if ((unsigned)(dx2+1) < 21u) Dsm[(dx2+1)*80 + m0+8] = dacc[t][3];
        }
        __syncthreads();

        // coalesced store of 21 x 80 band rows (160 threads)
        {
            const int mloc = (tid >= 80) ? tid - 80 : tid;
            const int dxi0 = (tid >= 80) ? 1 : 0;
            float* orow = g_raw + ((size_t)(b*441 + pane*21) * 158 + y) * 160
                          + p*80 + mloc;
            #pragma unroll
            for (int k = 0; k < 10; ++k){
                int dxi = 2*k + dxi0;
                orow[(size_t)dxi * CH_STRIDE] = Dsm[dxi*80 + mloc];
            }
            if (dxi0 == 0)
                orow[(size_t)20 * CH_STRIDE] = Dsm[20*80 + mloc];
        }
        // next pane's top sync orders these Dsm reads before rewrite
    }
}

// ---------------- Pass 2: 3x3 box sum / 1152 on parity-split rows ----------------
__global__ void corr_pass2(float* __restrict__ out){
    const int tid = threadIdx.x;            // 156
    const int qx = tid % 39;
    const int qy = blockIdx.y * 4 + tid / 39;
    const int ch = blockIdx.z;
    if (qy >= 39) return;
    const int i0 = qy * 4, j0 = qx * 4, m0 = qx * 2;
    const float inv = 1.0f / 1152.0f;

    const float* rb = g_raw + (size_t)ch * CH_STRIDE;
    float w6[6][4];
    #pragma unroll
    for (int rr = 0; rr < 6; ++rr){
        const float* row = rb + (size_t)(i0 + rr) * 160;
        float2 u = *(const float2*)(row + m0);
        float  u2 = row[m0 + 2];
        float2 v = *(const float2*)(row + 80 + m0);
        float  v2 = row[80 + m0 + 2];
        w6[rr][0] = u.x + v.x + u.y;
        w6[rr][1] = v.x + u.y + v.y;
        w6[rr][2] = u.y + v.y + u2;
        w6[rr][3] = v.y + u2 + v2;
    }
    float* ob = out + (size_t)ch * HO * WO + j0;
    #pragma unroll
    for (int i = 0; i < 4; ++i){
        float4 o;
        o.x = (w6[i][0] + w6[i+1][0] + w6[i+2][0]) * inv;
        o.y = (w6[i][1] + w6[i+1][1] + w6[i+2][1]) * inv;
        o.z = (w6[i][2] + w6[i+1][2] + w6[i+2][2]) * inv;
        o.w = (w6[i][3] + w6[i+1][3] + w6[i+2][3]) * inv;
        *reinterpret_cast<float4*>(ob + (size_t)(i0 + i) * WO) = o;
    }
}

extern "C" void kernel_launch(void* const* d_in, const int* in_sizes, int n_in,
                              void* d_out, int out_size){
    const float* in1 = (const float*)d_in[0];
    const float* in2 = (const float*)d_in[1];
    float* out = (float*)d_out;

    transAB<<<dim3(356, 4), 256>>>(in1, in2);

    cudaFuncSetAttribute(corr_mma,
                         cudaFuncAttributeMaxDynamicSharedMemorySize, SMEM_TOTAL);
    corr_mma<<<dim3(158, 2, 4), 160, SMEM_TOTAL>>>();

    dim3 g2(1, 10, 4*441), b2(156);
    corr_pass2<<<g2, b2>>>(out);
}

// round 14
// speedup vs baseline: 1.9176x; 1.1645x over previous
#include <cuda_runtime.h>
#include <cstdint>

#define HR 158
#define HO 156
#define WO 156
#define CH_STRIDE (158*160)

// smem map (bytes): B double-buffer (frag-ordered halves) + band tile
#define SM_B0  0
#define BHALF  26624                 // 13 T x 8 ksl x 32 lanes x 8B
#define SM_DS  (2*BHALF)             // 53248
#define SMEM_TOTAL (SM_DS + 21*80*4) // 59968  (x3 CTAs = 180 KB < 228 KB)

// At frag-ordered: [b][y 158][p 2] x [mt 5][ks 16][lane 32][4]  (10240 f/pane)
__device__ __align__(16) float g_At[(size_t)4*158*2*10240];
// Bt frag-ordered: [b][y2i 198][p 2] x [kh 2][T 13][ksl 8][lane 32][2] (13312 f/pane)
__device__ __align__(16) float g_Bt[(size_t)4*198*2*13312];
// raw, parity-split rows: [b*441+ch][y 158][p 2][m 80]  (~178 MB)
__device__ __align__(16) float g_raw[(size_t)4*441*158*160];

static __device__ __forceinline__ float to_tf32(float x){
    float r; asm("cvt.rna.tf32.f32 %0, %1;" : "=f"(r) : "f"(x)); return r;
}

// ---------------- Pass 0: fused transpose/pad into FRAGMENT-ORDER tiles ------
// grid.x: [0,158) -> A row y ; [158,356) -> B row y2i. grid.y = b.
__global__ __launch_bounds__(256) void transAB(const float* __restrict__ in1,
                                               const float* __restrict__ in2){
    __shared__ float sm[32*193];
    const int bx = blockIdx.x, b = blockIdx.y;
    const int tid = threadIdx.x;

    if (bx < 158){
        const int y = bx;
        float* outp = g_At + (size_t)((b*158 + y)*2) * 10240;
        for (int cc = 0; cc < 4; ++cc){
            const int c0 = cc*32;
            __syncthreads();
            for (int idx = tid; idx < 32*192; idx += 256){
                int cl = idx / 192, xx = idx - cl*192;
                sm[cl*193 + xx] = in1[(((size_t)b*128 + c0 + cl)*192 + (y+17))*192 + xx];
            }
            __syncthreads();
            // 1280 float4 frag words: v -> (pp, mt, ks_l, lane)
            #pragma unroll
            for (int it = 0; it < 5; ++it){
                int v = tid + it*256;
                int lane = v & 31;
                int q = v >> 5;            // 0..39
                int ks_l = q & 3; q >>= 2; // 0..9
                int mt = q % 5, pp = q / 5;
                int grp = lane >> 2, tig = lane & 3;
                int m = 16*mt + grp;               // <= 71
                int x = 2*m + pp + 17;             // <= 160
                int cl = ks_l*8 + tig;
                float4 o;
                o.x = to_tf32(sm[cl*193 + x]);
                o.z = to_tf32(sm[(cl+4)*193 + x]);
                if (m + 8 <= 78){
                    o.y = to_tf32(sm[cl*193 + x + 16]);
                    o.w = to_tf32(sm[(cl+4)*193 + x + 16]);
                } else { o.y = 0.f; o.w = 0.f; }
                int ks = cc*4 + ks_l;
                float* dst = outp + (size_t)pp*10240 + ((mt*16 + ks)*32 + lane)*4;
                *reinterpret_cast<float4*>(dst) = o;
            }
        }
    } else {
        const int y2i = bx - 158;
        const int y2 = y2i - 3;
        const bool rowok = (y2 >= 0 && y2 < 192);
        float* outp = g_Bt + (size_t)((b*198 + y2i)*2) * 13312;
        for (int cc = 0; cc < 4; ++cc){
            const int c0 = cc*32;
            __syncthreads();
            for (int idx = tid; idx < 32*192; idx += 256){
                int cl = idx / 192, xx = idx - cl*192;
                sm[cl*193 + xx] = rowok ?
                    in2[(((size_t)b*128 + c0 + cl)*192 + y2)*192 + xx] : 0.f;
            }
            __syncthreads();
            // 3328 float2 frag words: v -> (pp, T, ks_l, lane)
            const int kh = cc >> 1, kslc = (cc & 1)*4;
            #pragma unroll
            for (int it = 0; it < 13; ++it){
                int v = tid + it*256;
                int lane = v & 31;
                int q = v >> 5;            // 0..103
                int ks_l = q & 3; q >>= 2; // 0..25
                int T = q % 13, pp = q / 13;
                int grp = lane >> 2, tig = lane & 3;
                int n = T*8 + grp;
                int x = 2*n + pp - 3;
                int cl = ks_l*8 + tig;
                float2 o;
                o.x = ((unsigned)x < 192u) ? to_tf32(sm[cl*193 + x]) : 0.f;
                o.y = ((unsigned)x < 192u) ? to_tf32(sm[(cl+4)*193 + x]) : 0.f;
                int ksl = kslc + ks_l;
                float* dst = outp + (size_t)pp*13312 +
                             (((kh*13 + T)*8 + ksl)*32 + lane)*2;
                *reinterpret_cast<float2*>(dst) = o;
            }
        }
    }
}

// ---------------- helpers ----------------
__device__ __forceinline__ void cpa16(uint32_t dst, const void* src){
    asm volatile("cp.async.cg.shared.global [%0], [%1], 16;" :: "r"(dst), "l"(src));
}
__device__ __forceinline__ void mma8(float* d, const uint32_t* a, uint32_t b0, uint32_t b1){
    asm volatile(
        "mma.sync.aligned.m16n8k8.row.col.f32.tf32.tf32.f32 "
        "{%0,%1,%2,%3}, {%4,%5,%6,%7}, {%8,%9}, {%0,%1,%2,%3};"
        : "+f"(d[0]), "+f"(d[1]), "+f"(d[2]), "+f"(d[3])
        : "r"(a[0]), "r"(a[1]), "r"(a[2]), "r"(a[3]), "r"(b0), "r"(b1));
}

// ---------------- Pass 1: banded tf32 MMA, frag-order operands, 3 CTA/SM ----
// grid (y 158, p 2, b 4); block 160 = 5 warps, warp w owns m-rows 16w..16w+15
// and its 5 diagonal n8-tiles (T = 2w+t). B pane in two 64-channel halves.
extern __shared__ __align__(16) char smem_dyn[];

__global__ __launch_bounds__(160, 3)
void corr_mma(){
    const int y = blockIdx.x, p = blockIdx.y, b = blockIdx.z;
    const int tid = threadIdx.x, w = tid >> 5, lane = tid & 31;
    const int grp = lane >> 2, tig = lane & 3;
    char* smc = smem_dyn;
    const uint32_t sb = (uint32_t)__cvta_generic_to_shared(smc);
    float* Dsm = (float*)(smc + SM_DS);

    const float* Ap = g_At + ((size_t)(b*158 + y)*2 + p) * 10240;
    const size_t bbase = ((size_t)b*198 + y)*2 + p;
    const int m0 = 16*w + grp;

    // prologue: B(pane0, kh0) cp.async as group 0 (linear 26624B copy)
    {
        const char* Bb = (const char*)(g_Bt + bbase * 13312);
        for (int idx = tid; idx < 1664; idx += 160)
            cpa16(sb + SM_B0 + idx*16, Bb + idx*16);
    }
    asm volatile("cp.async.commit_group;" ::: "memory");

    // A fragments: 16 coalesced LDG.128 per thread
    uint32_t areg[64];
    {
        const uint4* Af = (const uint4*)Ap;
        #pragma unroll
        for (int ks = 0; ks < 16; ++ks){
            uint4 f = __ldg(&Af[(w*16 + ks)*32 + lane]);
            areg[ks*4+0] = f.x; areg[ks*4+1] = f.y;
            areg[ks*4+2] = f.z; areg[ks*4+3] = f.w;
        }
    }

    for (int pane = 0; pane <= 20; ++pane){
        float dacc[5][4];
        #pragma unroll
        for (int t = 0; t < 5; ++t)
            #pragma unroll
            for (int q = 0; q < 4; ++q) dacc[t][q] = 0.f;

        #pragma unroll
        for (int kh = 0; kh < 2; ++kh){
            const int ph = pane*2 + kh;

            asm volatile("cp.async.wait_group 0;" ::: "memory");
            __syncthreads();

            if (ph < 41){
                const int npane = (ph+1) >> 1, nkh = (ph+1) & 1;
                const char* Bb = (const char*)(g_Bt +
                    (bbase + (size_t)npane*4) * 13312) + nkh*BHALF;
                const uint32_t dstb = sb + SM_B0 + ((ph+1) & 1) * BHALF;
                for (int idx = tid; idx < 1664; idx += 160)
                    cpa16(dstb + idx*16, Bb + idx*16);
                asm volatile("cp.async.commit_group;" ::: "memory");
            }

            const char* bufb = smc + SM_B0 + (ph & 1)*BHALF;
            #pragma unroll
            for (int ksl = 0; ksl < 8; ++ksl){
                const uint32_t* a = &areg[(kh*8 + ksl)*4];
                #pragma unroll
                for (int t = 0; t < 5; ++t){
                    const uint2 bw = *(const uint2*)(bufb +
                        ((2*w + t)*8 + ksl)*256 + lane*8);
                    mma8(dacc[t], a, bw.x, bw.y);
                }
            }
            // no bottom sync: next phase's top sync orders buffer reuse
        }

        // band extraction into Dsm[dxi][m]
        #pragma unroll
        for (int t = 0; t < 5; ++t){
            const int dx0 = 8*t + 2*tig - grp;
            if ((unsigned)dx0 < 21u)     Dsm[dx0*80 + m0]     = dacc[t][0];
            if ((unsigned)(dx0+1) < 21u) Dsm[(dx0+1)*80 + m0] = dacc[t][1];
            const int dx2 = dx0 - 8;
            if ((unsigned)dx2 < 21u)     Dsm[dx2*80 + m0+8]     = dacc[t][2];
            if ((unsigned)(dx2+1) < 21u) Dsm[(dx2+1)*80 + m0+8] = dacc[t][3];
        }
        __syncthreads();

        // coalesced store of 21 x 80 band rows (160 threads)
        {
            const int mloc = (tid >= 80) ? tid - 80 : tid;
            const int dxi0 = (tid >= 80) ? 1 : 0;
            float* orow = g_raw + ((size_t)(b*441 + pane*21) * 158 + y) * 160
                          + p*80 + mloc;
            #pragma unroll
            for (int k = 0; k < 10; ++k){
                int dxi = 2*k + dxi0;
                orow[(size_t)dxi * CH_STRIDE] = Dsm[dxi*80 + mloc];
            }
            if (dxi0 == 0)
                orow[(size_t)20 * CH_STRIDE] = Dsm[20*80 + mloc];
        }
        // next pane's top sync orders these Dsm reads before rewrite
    }
}

// ---------------- Pass 2: 3x3 box sum / 1152 on parity-split rows ----------------
__global__ void corr_pass2(float* __restrict__ out){
    const int tid = threadIdx.x;            // 156
    const int qx = tid % 39;
    const int qy = blockIdx.y * 4 + tid / 39;
    const int ch = blockIdx.z;
    if (qy >= 39) return;
    const int i0 = qy * 4, j0 = qx * 4, m0 = qx * 2;
    const float inv = 1.0f / 1152.0f;

    const float* rb = g_raw + (size_t)ch * CH_STRIDE;
    float w6[6][4];
    #pragma unroll
    for (int rr = 0; rr < 6; ++rr){
        const float* row = rb + (size_t)(i0 + rr) * 160;
        float2 u = *(const float2*)(row + m0);
        float  u2 = row[m0 + 2];
        float2 v = *(const float2*)(row + 80 + m0);
        float  v2 = row[80 + m0 + 2];
        w6[rr][0] = u.x + v.x + u.y;
        w6[rr][1] = v.x + u.y + v.y;
        w6[rr][2] = u.y + v.y + u2;
        w6[rr][3] = v.y + u2 + v2;
    }
    float* ob = out + (size_t)ch * HO * WO + j0;
    #pragma unroll
    for (int i = 0; i < 4; ++i){
        float4 o;
        o.x = (w6[i][0] + w6[i+1][0] + w6[i+2][0]) * inv;
        o.y = (w6[i][1] + w6[i+1][1] + w6[i+2][1]) * inv;
        o.z = (w6[i][2] + w6[i+1][2] + w6[i+2][2]) * inv;
        o.w = (w6[i][3] + w6[i+1][3] + w6[i+2][3]) * inv;
        *reinterpret_cast<float4*>(ob + (size_t)(i0 + i) * WO) = o;
    }
}

extern "C" void kernel_launch(void* const* d_in, const int* in_sizes, int n_in,
                              void* d_out, int out_size){
    const float* in1 = (const float*)d_in[0];
    const float* in2 = (const float*)d_in[1];
    float* out = (float*)d_out;

    transAB<<<dim3(356, 4), 256>>>(in1, in2);

    cudaFuncSetAttribute(corr_mma,
                         cudaFuncAttributeMaxDynamicSharedMemorySize, SMEM_TOTAL);
    corr_mma<<<dim3(158, 2, 4), 160, SMEM_TOTAL>>>();

    dim3 g2(1, 10, 4*441), b2(156);
    corr_pass2<<<g2, b2>>>(out);
}